// round 13
// baseline (speedup 1.0000x reference)
#include <cuda_runtime.h>

#define NB   16384
#define NJ   12
#define NQ   7
#define NO   5
#define NH1  128
#define NH2  128
#define GS   4
#define NBLOCKS (NB / GS)

#define W1_SZ (NQ * (NO + 1) * NH1)     // 5376
#define W2P_SZ ((NH1 + 1) * NH2)        // 16512 floats = 129 rows x 64 float2 pairs
#define VT_ROW 132                      // [bias, w_1..w_128, 0,0,0]
#define VT_SZ (NQ * NO * VT_ROW)        // 4620
#define ZSTR 28                         // z1 row stride in floats ([k][q][s])

#define PREP_BLOCKS 64
#define PREP_THREADS 256

// ---------------- device scratch ----------------
__device__ int    g_mode64;
__device__ int    g_count[NJ];          // zero-initialized; re-zeroed by k_scan
__device__ int    g_cursor[NJ];
__device__ int    g_perm[NB];
__device__ float  g_cW1[NJ * W1_SZ];    // [j][q][i=0..5][h]
__device__ float2 g_cW2p[NJ * (NH1 + 1) * 64];  // [j][i=0..128][pair p] = (w[h_lo], w[h_lo+32])
__device__ float  g_cVt[NJ * VT_SZ];    // [j][q][o][i=0..128,pad]

// ---------------- helpers ----------------
__device__ __forceinline__ float sigmoidf(float v) {
    return 1.0f / (1.0f + __expf(-v));
}
__device__ __forceinline__ unsigned long long pk(float a, float b) {
    unsigned long long r;
    asm("mov.b64 %0, {%1, %2};" : "=l"(r) : "f"(a), "f"(b));
    return r;
}
__device__ __forceinline__ void upk(unsigned long long v, float& lo, float& hi) {
    asm("mov.b64 {%0, %1}, %2;" : "=f"(lo), "=f"(hi) : "l"(v));
}
__device__ __forceinline__ void ffma2(unsigned long long& d,
                                      unsigned long long a,
                                      unsigned long long b) {
    asm("fma.rn.f32x2 %0, %1, %2, %0;" : "+l"(d) : "l"(a), "l"(b));
}

// ---------- detect judge-id dtype from the first 512 words ----------
__device__ __forceinline__ int detect_m64(const int* __restrict__ jw, int tid) {
    __shared__ int s_any;
    if (tid == 0) s_any = 0;
    __syncthreads();
    // int64 little-endian ids (0..11): every odd word is 0.
    if (jw[2 * (tid & 255) + 1] != 0) s_any = 1;   // benign race
    __syncthreads();
    return (s_any == 0);
}

// ================= prologue 1: histogram + dtype + weight combine =================
__global__ void __launch_bounds__(PREP_THREADS)
k_countw(const int* __restrict__ jw,
         const float* __restrict__ W1, const float* __restrict__ W1a,
         const float* __restrict__ W2, const float* __restrict__ W2a,
         const float* __restrict__ V,  const float* __restrict__ Va) {
    __shared__ int s_cnt[NJ];
    const int tid = threadIdx.x;
    const int b = blockIdx.x * PREP_THREADS + tid;

    const int m64 = detect_m64(jw, tid);
    if (blockIdx.x == 0 && tid == 0) g_mode64 = m64;

    if (tid < NJ) s_cnt[tid] = 0;
    __syncthreads();
    const int j = m64 ? jw[2 * b] : jw[b];
    atomicAdd(&s_cnt[j], 1);
    __syncthreads();
    if (tid < NJ && s_cnt[tid]) atomicAdd(&g_count[tid], s_cnt[tid]);

    const int n1 = NJ * W1_SZ;
    const int n2 = NJ * W2P_SZ;
    const int n3 = NJ * VT_SZ;
    const int total = n1 + n2 + n3;
    float* w2p = (float*)g_cW2p;
    for (int i = blockIdx.x * PREP_THREADS + tid; i < total;
         i += PREP_BLOCKS * PREP_THREADS) {
        if (i < n1) {
            g_cW1[i] = W1[i % W1_SZ] + W1a[i];
        } else if (i < n1 + n2) {
            int r  = i - n1;                  // [j][i-row][pc], pc in [0,128)
            int jj = r / W2P_SZ;
            int rem = r % W2P_SZ;
            int ii = rem / 128;               // 0 = bias row, 1..128
            int pc = rem % 128;
            int p  = pc >> 1, c = pc & 1;
            int h  = ((p >> 5) << 6) + (p & 31) + (c << 5);  // pair (h_lo, h_lo+32)
            w2p[r] = W2[ii * 128 + h] + W2a[jj * W2P_SZ + ii * 128 + h];
        } else {
            int r = i - n1 - n2;
            int ii = r % VT_ROW;              // 0 = bias, 1..128 = weights
            int rr = r / VT_ROW;              // ((j*NQ+q)*NO+o)
            int o  = rr % NO;
            int qq = (rr / NO) % NQ;
            int jj = rr / (NO * NQ);
            float v = 0.0f;
            if (ii <= NH2)
                v = V[(qq * (NH2 + 1) + ii) * NO + o] +
                    Va[((jj * NQ + qq) * (NH2 + 1) + ii) * NO + o];
            g_cVt[r] = v;
        }
    }
}

// ================= prologue 2: scan + reset =================
__global__ void k_scan() {
    if (threadIdx.x == 0) {
        int acc = 0;
        #pragma unroll
        for (int k = 0; k < NJ; k++) {
            g_cursor[k] = acc;
            acc += g_count[k];
            g_count[k] = 0;
        }
    }
}

// ================= prologue 3: scatter =================
__global__ void __launch_bounds__(PREP_THREADS)
k_scatter(const int* __restrict__ jw) {
    const int tid = threadIdx.x;
    const int b = blockIdx.x * PREP_THREADS + tid;
    const int j = g_mode64 ? jw[2 * b] : jw[b];
    int pos = atomicAdd(&g_cursor[j], 1);
    g_perm[pos] = b;
}

// ================= templated MLP body (UNI = all 4 samples same judge) =================
template <bool UNI>
__device__ __forceinline__ void mlp_body(
    int tid, const int* __restrict__ sj, const int* __restrict__ sb,
    const float* __restrict__ xs2, float* __restrict__ zbuf,
    const float* __restrict__ sVt, float (*__restrict__ lg)[NO],
    float* __restrict__ out) {

    const int j0 = sj[0];
    const float* b1_0 = g_cW1 + j0 * W1_SZ;
    const float* b1_1 = UNI ? b1_0 : g_cW1 + sj[1] * W1_SZ;
    const float* b1_2 = UNI ? b1_0 : g_cW1 + sj[2] * W1_SZ;
    const float* b1_3 = UNI ? b1_0 : g_cW1 + sj[3] * W1_SZ;

    // ---------- layer 1: thread = h column, all (s,q) ----------
    float a1[GS][NQ];
    #pragma unroll
    for (int q = 0; q < NQ; q++) {
        {   // i = 0 (bias)
            int off = (q * (NO + 1)) * NH1 + tid;
            a1[0][q] = b1_0[off];
            a1[1][q] = UNI ? a1[0][q] : b1_1[off];
            a1[2][q] = UNI ? a1[0][q] : b1_2[off];
            a1[3][q] = UNI ? a1[0][q] : b1_3[off];
        }
        #pragma unroll
        for (int i = 1; i <= NO; i++) {
            int off = (q * (NO + 1) + i) * NH1 + tid;
            float w0 = b1_0[off];
            float w1 = UNI ? w0 : b1_1[off];
            float w2 = UNI ? w0 : b1_2[off];
            float w3 = UNI ? w0 : b1_3[off];
            float4 xv = *(const float4*)(xs2 + (q * NO + i - 1) * GS);
            a1[0][q] = fmaf(xv.x, w0, a1[0][q]);
            a1[1][q] = fmaf(xv.y, w1, a1[1][q]);
            a1[2][q] = fmaf(xv.z, w2, a1[2][q]);
            a1[3][q] = fmaf(xv.w, w3, a1[3][q]);
        }
    }
    // store z1 row [k=tid][q][s] as 7 x STS.128 (conflict-free)
    #pragma unroll
    for (int q = 0; q < NQ; q++) {
        float4 v = { sigmoidf(a1[0][q]), sigmoidf(a1[1][q]),
                     sigmoidf(a1[2][q]), sigmoidf(a1[3][q]) };
        *(float4*)(zbuf + tid * ZSTR + q * 4) = v;
    }
    __syncthreads();

    // ---------- layer 2: warps 0-1 only; lane owns h-pair (h0, h0+32) ----------
    // acc0 = h0 accumulators, acc1 = h1; each [q][s-pair] packed f32x2.
    unsigned long long acc0[NQ][2], acc1[NQ][2];
    if (tid < 64) {
        const int p = tid;                       // pair index 0..63
        const float2* wpA = g_cW2p + (size_t)j0 * ((NH1 + 1) * 64) + p;
        const float2* wpB = UNI ? wpA : g_cW2p + (size_t)sj[1] * ((NH1 + 1) * 64) + p;
        const float2* wpC = UNI ? wpA : g_cW2p + (size_t)sj[2] * ((NH1 + 1) * 64) + p;
        const float2* wpD = UNI ? wpA : g_cW2p + (size_t)sj[3] * ((NH1 + 1) * 64) + p;

        {   // bias row i = 0
            float2 wa = wpA[0];
            unsigned long long m00, m01, m10, m11;
            if (UNI) {
                m00 = pk(wa.x, wa.x); m01 = m00;
                m10 = pk(wa.y, wa.y); m11 = m10;
            } else {
                float2 wb = wpB[0], wc = wpC[0], wd = wpD[0];
                m00 = pk(wa.x, wb.x); m01 = pk(wc.x, wd.x);
                m10 = pk(wa.y, wb.y); m11 = pk(wc.y, wd.y);
            }
            #pragma unroll
            for (int q = 0; q < NQ; q++) {
                acc0[q][0] = m00; acc0[q][1] = m01;
                acc1[q][0] = m10; acc1[q][1] = m11;
            }
        }
        #pragma unroll 2
        for (int i = 1; i <= NH1; i++) {
            float2 wa = wpA[i * 64];
            unsigned long long m00, m01, m10, m11;
            if (UNI) {
                m00 = pk(wa.x, wa.x); m01 = m00;
                m10 = pk(wa.y, wa.y); m11 = m10;
            } else {
                float2 wb = wpB[i * 64], wc = wpC[i * 64], wd = wpD[i * 64];
                m00 = pk(wa.x, wb.x); m01 = pk(wc.x, wd.x);
                m10 = pk(wa.y, wb.y); m11 = pk(wc.y, wd.y);
            }
            const ulonglong2* zr = (const ulonglong2*)(zbuf + (i - 1) * ZSTR);
            #pragma unroll
            for (int q = 0; q < NQ; q++) {
                ulonglong2 z = zr[q];      // {z[s0],z[s1]}, {z[s2],z[s3]}
                ffma2(acc0[q][0], z.x, m00);
                ffma2(acc0[q][1], z.y, m01);
                ffma2(acc1[q][0], z.x, m10);
                ffma2(acc1[q][1], z.y, m11);
            }
        }
    }
    __syncthreads();   // all z1 reads done before z2 overlays zbuf

    if (tid < 64) {
        const int h0 = ((tid >> 5) << 6) + (tid & 31);   // 0..31 / 64..95
        const int h1 = h0 + 32;
        #pragma unroll
        for (int q = 0; q < NQ; q++) {
            float f0, f1, f2, f3;
            upk(acc0[q][0], f0, f1);
            upk(acc0[q][1], f2, f3);
            zbuf[(0 * NQ + q) * VT_ROW + 1 + h0] = sigmoidf(f0);
            zbuf[(1 * NQ + q) * VT_ROW + 1 + h0] = sigmoidf(f1);
            zbuf[(2 * NQ + q) * VT_ROW + 1 + h0] = sigmoidf(f2);
            zbuf[(3 * NQ + q) * VT_ROW + 1 + h0] = sigmoidf(f3);
            upk(acc1[q][0], f0, f1);
            upk(acc1[q][1], f2, f3);
            zbuf[(0 * NQ + q) * VT_ROW + 1 + h1] = sigmoidf(f0);
            zbuf[(1 * NQ + q) * VT_ROW + 1 + h1] = sigmoidf(f1);
            zbuf[(2 * NQ + q) * VT_ROW + 1 + h1] = sigmoidf(f2);
            zbuf[(3 * NQ + q) * VT_ROW + 1 + h1] = sigmoidf(f3);
        }
    }
    if (tid < GS * NQ) {                 // bias + zero pads
        float* row = zbuf + tid * VT_ROW;
        row[0] = 1.0f; row[129] = 0.0f; row[130] = 0.0f; row[131] = 0.0f;
    }
    if (UNI) asm volatile("cp.async.wait_group 0;" ::: "memory");
    __syncthreads();

    // ---------- layer 3: logits ----------
    for (int t = tid; t < GS * NQ * NO; t += 128) {
        int s = t / (NQ * NO), r = t % (NQ * NO), q = r / NO, o = r % NO;
        const ulonglong2* vz = (const ulonglong2*)(zbuf + (s * NQ + q) * VT_ROW);
        const ulonglong2* vv = UNI
            ? (const ulonglong2*)(sVt + (q * NO + o) * VT_ROW)
            : (const ulonglong2*)(g_cVt + (sj[s] * NQ * NO + q * NO + o) * VT_ROW);
        unsigned long long s0 = 0ULL, s1 = 0ULL;
        #pragma unroll
        for (int k = 0; k < VT_ROW / 4; k++) {
            ulonglong2 a = vz[k], bb = vv[k];
            ffma2(s0, a.x, bb.x);
            ffma2(s1, a.y, bb.y);
        }
        float f0, f1, f2, f3;
        upk(s0, f0, f1);
        upk(s1, f2, f3);
        lg[s * NQ + q][o] = (f0 + f1) + (f2 + f3);
    }
    __syncthreads();

    // ---------- softmax + store ----------
    if (tid < GS * NQ) {
        int s = tid / NQ, q = tid % NQ;
        float m = lg[tid][0];
        #pragma unroll
        for (int o = 1; o < NO; o++) m = fmaxf(m, lg[tid][o]);
        float e[NO], sum = 0.f;
        #pragma unroll
        for (int o = 0; o < NO; o++) { e[o] = __expf(lg[tid][o] - m); sum += e[o]; }
        float inv = 1.0f / sum;
        float* op = out + (sb[s] * NQ + q) * NO;
        #pragma unroll
        for (int o = 0; o < NO; o++) op[o] = e[o] * inv;
    }
}

// ================= fused MLP, GS same-judge samples per block =================
__global__ void __launch_bounds__(128)
k_main(const float* __restrict__ x, const int* __restrict__ jw,
       float* __restrict__ out) {
    __shared__ int   sb[GS], sj[GS];
    __shared__ __align__(16) float xs2[NQ * NO * GS];    // [q][o][s0..s3]
    // union: layer1 z1 [k][q][s] (3584 f)  then  z2 [28][VT_ROW] (3696 f)
    __shared__ __align__(16) float zbuf[GS * NQ * VT_ROW];
    __shared__ __align__(16) float sVt[VT_SZ];           // this judge's V^T
    __shared__ float lg[GS * NQ][NO];

    const int tid = threadIdx.x;

    if (tid < GS) {
        int b = g_perm[blockIdx.x * GS + tid];
        sb[tid] = b;
        sj[tid] = g_mode64 ? jw[2 * b] : jw[b];
    }
    __syncthreads();

    const bool uni = (sj[0] == sj[1]) & (sj[1] == sj[2]) & (sj[2] == sj[3]);

    // async prefetch of this judge's V^T (consumed only in layer 3)
    if (uni) {
        unsigned sdst = (unsigned)__cvta_generic_to_shared(sVt);
        unsigned long long gsrc;
        const float* p = g_cVt + sj[0] * VT_SZ;
        asm("cvta.to.global.u64 %0, %1;" : "=l"(gsrc) : "l"(p));
        for (int t = tid; t < VT_SZ / 4; t += 128)
            asm volatile("cp.async.ca.shared.global [%0], [%1], 16;"
                         :: "r"(sdst + t * 16), "l"(gsrc + (unsigned long long)t * 16));
        asm volatile("cp.async.commit_group;");
    }

    // stage x transposed: xs2[(q*5+o)*4 + s]
    for (int t = tid; t < GS * NQ * NO; t += 128) {
        int s = t / (NQ * NO), r = t % (NQ * NO);
        xs2[r * GS + s] = x[sb[s] * (NQ * NO) + r];
    }
    __syncthreads();

    if (uni) mlp_body<true >(tid, sj, sb, xs2, zbuf, sVt, lg, out);
    else     mlp_body<false>(tid, sj, sb, xs2, zbuf, sVt, lg, out);
}

// ---------------- launch ----------------
extern "C" void kernel_launch(void* const* d_in, const int* in_sizes, int n_in,
                              void* d_out, int out_size) {
    const float* x   = (const float*)d_in[0];
    const int*   jw  = (const int*)  d_in[1];
    const float* W1  = (const float*)d_in[2];
    const float* W1a = (const float*)d_in[3];
    const float* W2  = (const float*)d_in[4];
    const float* W2a = (const float*)d_in[5];
    const float* V   = (const float*)d_in[6];
    const float* Va  = (const float*)d_in[7];
    float* out = (float*)d_out;

    k_countw <<<PREP_BLOCKS, PREP_THREADS>>>(jw, W1, W1a, W2, W2a, V, Va);
    k_scan   <<<1, 32>>>();
    k_scatter<<<PREP_BLOCKS, PREP_THREADS>>>(jw);
    k_main   <<<NBLOCKS, 128>>>(x, jw, out);
}

// round 14
// speedup vs baseline: 1.6588x; 1.6588x over previous
#include <cuda_runtime.h>

#define NB   16384
#define NJ   12
#define NQ   7
#define NO   5
#define NH1  128
#define NH2  128
#define GS   4
#define NBLOCKS (NB / GS)

#define W1_SZ (NQ * (NO + 1) * NH1)     // 5376
#define W2P_SZ ((NH1 + 1) * NH2)        // 16512 floats
#define W2P_F2 ((NH1 + 1) * 64)         // float2 stride per judge
#define VT_ROW 132                      // [bias, w_1..w_128, 0,0,0]
#define VT_SZ (NQ * NO * VT_ROW)        // 4620
#define ZSTR 36                         // z1 row stride in floats ([k][sp][qpairs])
#define ZBUF_SZ (NH1 * ZSTR)            // 4608 >= 28*VT_ROW (3696)

#define PREP_BLOCKS 64
#define PREP_THREADS 256

// ---------------- device scratch ----------------
__device__ int    g_mode64;
__device__ int    g_count[NJ];          // zero-initialized; re-zeroed by k_scan
__device__ int    g_cursor[NJ];
__device__ int    g_perm[NB];
__device__ float  g_cW1[NJ * W1_SZ];    // [j][q][i=0..5][h]
__device__ float2 g_cW2p[NJ * W2P_F2];  // [j][i=0..128][pair p] = (w[h_lo], w[h_lo+32])
__device__ float  g_cVt[NJ * VT_SZ];    // [j][q][o][i=0..128,pad]

// ---------------- helpers ----------------
__device__ __forceinline__ float sigmoidf(float v) {
    return 1.0f / (1.0f + __expf(-v));
}
__device__ __forceinline__ unsigned long long pk(float a, float b) {
    unsigned long long r;
    asm("mov.b64 %0, {%1, %2};" : "=l"(r) : "f"(a), "f"(b));
    return r;
}
__device__ __forceinline__ void upk(unsigned long long v, float& lo, float& hi) {
    asm("mov.b64 {%0, %1}, %2;" : "=f"(lo), "=f"(hi) : "l"(v));
}
__device__ __forceinline__ void ffma2(unsigned long long& d,
                                      unsigned long long a,
                                      unsigned long long b) {
    asm("fma.rn.f32x2 %0, %1, %2, %0;" : "+l"(d) : "l"(a), "l"(b));
}

// ---------- detect judge-id dtype from the first 512 words ----------
__device__ __forceinline__ int detect_m64(const int* __restrict__ jw, int tid) {
    __shared__ int s_any;
    if (tid == 0) s_any = 0;
    __syncthreads();
    // int64 little-endian ids (0..11): every odd word is 0.
    if (jw[2 * (tid & 255) + 1] != 0) s_any = 1;   // benign race
    __syncthreads();
    return (s_any == 0);
}

// ================= prologue 1: histogram + dtype + weight combine =================
__global__ void __launch_bounds__(PREP_THREADS)
k_countw(const int* __restrict__ jw,
         const float* __restrict__ W1, const float* __restrict__ W1a,
         const float* __restrict__ W2, const float* __restrict__ W2a,
         const float* __restrict__ V,  const float* __restrict__ Va) {
    __shared__ int s_cnt[NJ];
    const int tid = threadIdx.x;
    const int b = blockIdx.x * PREP_THREADS + tid;

    const int m64 = detect_m64(jw, tid);
    if (blockIdx.x == 0 && tid == 0) g_mode64 = m64;

    if (tid < NJ) s_cnt[tid] = 0;
    __syncthreads();
    const int j = m64 ? jw[2 * b] : jw[b];
    atomicAdd(&s_cnt[j], 1);
    __syncthreads();
    if (tid < NJ && s_cnt[tid]) atomicAdd(&g_count[tid], s_cnt[tid]);

    const int n1 = NJ * W1_SZ;
    const int n2 = NJ * W2P_SZ;
    const int n3 = NJ * VT_SZ;
    const int total = n1 + n2 + n3;
    float* w2p = (float*)g_cW2p;
    for (int i = blockIdx.x * PREP_THREADS + tid; i < total;
         i += PREP_BLOCKS * PREP_THREADS) {
        if (i < n1) {
            g_cW1[i] = W1[i % W1_SZ] + W1a[i];
        } else if (i < n1 + n2) {
            int r  = i - n1;                  // [j][i-row][pc], pc in [0,128)
            int jj = r / W2P_SZ;
            int rem = r % W2P_SZ;
            int ii = rem / 128;               // 0 = bias row, 1..128
            int pc = rem % 128;
            int p  = pc >> 1, c = pc & 1;
            int h  = ((p >> 5) << 6) + (p & 31) + (c << 5);  // pair (h_lo, h_lo+32)
            w2p[r] = W2[ii * 128 + h] + W2a[jj * W2P_SZ + ii * 128 + h];
        } else {
            int r = i - n1 - n2;
            int ii = r % VT_ROW;              // 0 = bias, 1..128 = weights
            int rr = r / VT_ROW;              // ((j*NQ+q)*NO+o)
            int o  = rr % NO;
            int qq = (rr / NO) % NQ;
            int jj = rr / (NO * NQ);
            float v = 0.0f;
            if (ii <= NH2)
                v = V[(qq * (NH2 + 1) + ii) * NO + o] +
                    Va[((jj * NQ + qq) * (NH2 + 1) + ii) * NO + o];
            g_cVt[r] = v;
        }
    }
}

// ================= prologue 2: scan + reset =================
__global__ void k_scan() {
    if (threadIdx.x == 0) {
        int acc = 0;
        #pragma unroll
        for (int k = 0; k < NJ; k++) {
            g_cursor[k] = acc;
            acc += g_count[k];
            g_count[k] = 0;
        }
    }
}

// ================= prologue 3: scatter =================
__global__ void __launch_bounds__(PREP_THREADS)
k_scatter(const int* __restrict__ jw) {
    const int tid = threadIdx.x;
    const int b = blockIdx.x * PREP_THREADS + tid;
    const int j = g_mode64 ? jw[2 * b] : jw[b];
    int pos = atomicAdd(&g_cursor[j], 1);
    g_perm[pos] = b;
}

// ================= templated MLP body (UNI = all 4 samples same judge) =================
template <bool UNI>
__device__ __forceinline__ void mlp_body(
    int tid, const int* __restrict__ sj, const int* __restrict__ sb,
    const float* __restrict__ xs2, float* __restrict__ zbuf,
    const float* __restrict__ sVt, float (*__restrict__ lg)[NO],
    float* __restrict__ out) {

    const int j0 = sj[0];
    const float* b1_0 = g_cW1 + j0 * W1_SZ;
    const float* b1_1 = UNI ? b1_0 : g_cW1 + sj[1] * W1_SZ;
    const float* b1_2 = UNI ? b1_0 : g_cW1 + sj[2] * W1_SZ;
    const float* b1_3 = UNI ? b1_0 : g_cW1 + sj[3] * W1_SZ;

    // ---------- layer 1: thread = z1 row k (= hidden col), all (s,q) ----------
    float a1[GS][NQ];
    #pragma unroll
    for (int q = 0; q < NQ; q++) {
        {   // i = 0 (bias)
            int off = (q * (NO + 1)) * NH1 + tid;
            a1[0][q] = b1_0[off];
            a1[1][q] = UNI ? a1[0][q] : b1_1[off];
            a1[2][q] = UNI ? a1[0][q] : b1_2[off];
            a1[3][q] = UNI ? a1[0][q] : b1_3[off];
        }
        #pragma unroll
        for (int i = 1; i <= NO; i++) {
            int off = (q * (NO + 1) + i) * NH1 + tid;
            float w0 = b1_0[off];
            float w1 = UNI ? w0 : b1_1[off];
            float w2 = UNI ? w0 : b1_2[off];
            float w3 = UNI ? w0 : b1_3[off];
            float4 xv = *(const float4*)(xs2 + (q * NO + i - 1) * GS);
            a1[0][q] = fmaf(xv.x, w0, a1[0][q]);
            a1[1][q] = fmaf(xv.y, w1, a1[1][q]);
            a1[2][q] = fmaf(xv.z, w2, a1[2][q]);
            a1[3][q] = fmaf(xv.w, w3, a1[3][q]);
        }
    }
    // store z1 row [k=tid]: [sp0: (q0s0,q0s1,q1s0,q1s1)...(q6s0,q6s1,0,0) |
    //                        sp1: same with s2,s3]   -> 8 x STS.128
    {
        float* row = zbuf + tid * ZSTR;
        float4 c;
        c = make_float4(sigmoidf(a1[0][0]), sigmoidf(a1[1][0]),
                        sigmoidf(a1[0][1]), sigmoidf(a1[1][1]));
        *(float4*)(row + 0) = c;
        c = make_float4(sigmoidf(a1[0][2]), sigmoidf(a1[1][2]),
                        sigmoidf(a1[0][3]), sigmoidf(a1[1][3]));
        *(float4*)(row + 4) = c;
        c = make_float4(sigmoidf(a1[0][4]), sigmoidf(a1[1][4]),
                        sigmoidf(a1[0][5]), sigmoidf(a1[1][5]));
        *(float4*)(row + 8) = c;
        c = make_float4(sigmoidf(a1[0][6]), sigmoidf(a1[1][6]), 0.f, 0.f);
        *(float4*)(row + 12) = c;
        c = make_float4(sigmoidf(a1[2][0]), sigmoidf(a1[3][0]),
                        sigmoidf(a1[2][1]), sigmoidf(a1[3][1]));
        *(float4*)(row + 16) = c;
        c = make_float4(sigmoidf(a1[2][2]), sigmoidf(a1[3][2]),
                        sigmoidf(a1[2][3]), sigmoidf(a1[3][3]));
        *(float4*)(row + 20) = c;
        c = make_float4(sigmoidf(a1[2][4]), sigmoidf(a1[3][4]),
                        sigmoidf(a1[2][5]), sigmoidf(a1[3][5]));
        *(float4*)(row + 24) = c;
        c = make_float4(sigmoidf(a1[2][6]), sigmoidf(a1[3][6]), 0.f, 0.f);
        *(float4*)(row + 28) = c;
    }
    __syncthreads();

    // ---------- layer 2: warp = (sample-pair sp, h-half hw); lane owns (h0, h0+32)
    // acc0[q] packs (z2[h0][q][sA], z2[h0][q][sB]); acc1 = same for h1.
    const int wrp = tid >> 5;
    const int ln  = tid & 31;
    const int sp  = wrp >> 1;                 // 0: samples 0,1  1: samples 2,3
    const int hw  = wrp & 1;                  // h-half
    const int p   = hw * 32 + ln;             // weight-pair index
    const int sA  = 2 * sp, sB = 2 * sp + 1;

    const float2* wpA = g_cW2p + (size_t)(UNI ? j0 : sj[sA]) * W2P_F2 + p;
    const float2* wpB = UNI ? wpA : g_cW2p + (size_t)sj[sB] * W2P_F2 + p;

    unsigned long long acc0[NQ], acc1[NQ];
    {   // bias row i = 0
        float2 wa = wpA[0];
        unsigned long long m0, m1;
        if (UNI) { m0 = pk(wa.x, wa.x); m1 = pk(wa.y, wa.y); }
        else     { float2 wb = wpB[0]; m0 = pk(wa.x, wb.x); m1 = pk(wa.y, wb.y); }
        #pragma unroll
        for (int q = 0; q < NQ; q++) { acc0[q] = m0; acc1[q] = m1; }
    }
    #pragma unroll 4
    for (int i = 1; i <= NH1; i++) {
        float2 wa = wpA[i * 64];
        unsigned long long m0, m1;
        if (UNI) { m0 = pk(wa.x, wa.x); m1 = pk(wa.y, wa.y); }
        else     { float2 wb = wpB[i * 64]; m0 = pk(wa.x, wb.x); m1 = pk(wa.y, wb.y); }
        const float* zb = zbuf + (i - 1) * ZSTR + sp * 16;
        ulonglong2 zA = *(const ulonglong2*)(zb);       // q0, q1 pairs
        ulonglong2 zB = *(const ulonglong2*)(zb + 4);   // q2, q3
        ulonglong2 zC = *(const ulonglong2*)(zb + 8);   // q4, q5
        unsigned long long zD = *(const unsigned long long*)(zb + 12);  // q6
        ffma2(acc0[0], zA.x, m0); ffma2(acc1[0], zA.x, m1);
        ffma2(acc0[1], zA.y, m0); ffma2(acc1[1], zA.y, m1);
        ffma2(acc0[2], zB.x, m0); ffma2(acc1[2], zB.x, m1);
        ffma2(acc0[3], zB.y, m0); ffma2(acc1[3], zB.y, m1);
        ffma2(acc0[4], zC.x, m0); ffma2(acc1[4], zC.x, m1);
        ffma2(acc0[5], zC.y, m0); ffma2(acc1[5], zC.y, m1);
        ffma2(acc0[6], zD,   m0); ffma2(acc1[6], zD,   m1);
    }
    __syncthreads();   // all z1 reads done before z2 overlays zbuf

    {   // sigmoid -> z2 rows
        const int h0 = hw * 64 + ln;
        const int h1 = h0 + 32;
        #pragma unroll
        for (int q = 0; q < NQ; q++) {
            float eA, eB;
            upk(acc0[q], eA, eB);
            zbuf[(sA * NQ + q) * VT_ROW + 1 + h0] = sigmoidf(eA);
            zbuf[(sB * NQ + q) * VT_ROW + 1 + h0] = sigmoidf(eB);
            upk(acc1[q], eA, eB);
            zbuf[(sA * NQ + q) * VT_ROW + 1 + h1] = sigmoidf(eA);
            zbuf[(sB * NQ + q) * VT_ROW + 1 + h1] = sigmoidf(eB);
        }
    }
    if (tid < GS * NQ) {                 // bias + zero pads
        float* row = zbuf + tid * VT_ROW;
        row[0] = 1.0f; row[129] = 0.0f; row[130] = 0.0f; row[131] = 0.0f;
    }
    if (UNI) asm volatile("cp.async.wait_group 0;" ::: "memory");
    __syncthreads();

    // ---------- layer 3: logits ----------
    for (int t = tid; t < GS * NQ * NO; t += 128) {
        int s = t / (NQ * NO), r = t % (NQ * NO), q = r / NO, o = r % NO;
        const ulonglong2* vz = (const ulonglong2*)(zbuf + (s * NQ + q) * VT_ROW);
        const ulonglong2* vv = UNI
            ? (const ulonglong2*)(sVt + (q * NO + o) * VT_ROW)
            : (const ulonglong2*)(g_cVt + (sj[s] * NQ * NO + q * NO + o) * VT_ROW);
        unsigned long long s0 = 0ULL, s1 = 0ULL;
        #pragma unroll
        for (int k = 0; k < VT_ROW / 4; k++) {
            ulonglong2 a = vz[k], bb = vv[k];
            ffma2(s0, a.x, bb.x);
            ffma2(s1, a.y, bb.y);
        }
        float f0, f1, f2, f3;
        upk(s0, f0, f1);
        upk(s1, f2, f3);
        lg[s * NQ + q][o] = (f0 + f1) + (f2 + f3);
    }
    __syncthreads();

    // ---------- softmax + store ----------
    if (tid < GS * NQ) {
        int s = tid / NQ, q = tid % NQ;
        float m = lg[tid][0];
        #pragma unroll
        for (int o = 1; o < NO; o++) m = fmaxf(m, lg[tid][o]);
        float e[NO], sum = 0.f;
        #pragma unroll
        for (int o = 0; o < NO; o++) { e[o] = __expf(lg[tid][o] - m); sum += e[o]; }
        float inv = 1.0f / sum;
        float* op = out + (sb[s] * NQ + q) * NO;
        #pragma unroll
        for (int o = 0; o < NO; o++) op[o] = e[o] * inv;
    }
}

// ================= fused MLP, GS same-judge samples per block =================
__global__ void __launch_bounds__(128)
k_main(const float* __restrict__ x, const int* __restrict__ jw,
       float* __restrict__ out) {
    __shared__ int   sb[GS], sj[GS];
    __shared__ __align__(16) float xs2[NQ * NO * GS];    // [q][o][s0..s3]
    // union: layer1 z1 [k][sp][qpairs] (4608 f)  then  z2 [28][VT_ROW] (3696 f)
    __shared__ __align__(16) float zbuf[ZBUF_SZ];
    __shared__ __align__(16) float sVt[VT_SZ];           // this judge's V^T
    __shared__ float lg[GS * NQ][NO];

    const int tid = threadIdx.x;

    if (tid < GS) {
        int b = g_perm[blockIdx.x * GS + tid];
        sb[tid] = b;
        sj[tid] = g_mode64 ? jw[2 * b] : jw[b];
    }
    __syncthreads();

    const bool uni = (sj[0] == sj[1]) & (sj[1] == sj[2]) & (sj[2] == sj[3]);

    // async prefetch of this judge's V^T (consumed only in layer 3)
    if (uni) {
        unsigned sdst = (unsigned)__cvta_generic_to_shared(sVt);
        unsigned long long gsrc;
        const float* p = g_cVt + sj[0] * VT_SZ;
        asm("cvta.to.global.u64 %0, %1;" : "=l"(gsrc) : "l"(p));
        for (int t = tid; t < VT_SZ / 4; t += 128)
            asm volatile("cp.async.ca.shared.global [%0], [%1], 16;"
                         :: "r"(sdst + t * 16), "l"(gsrc + (unsigned long long)t * 16));
        asm volatile("cp.async.commit_group;");
    }

    // stage x transposed: xs2[(q*5+o)*4 + s]
    for (int t = tid; t < GS * NQ * NO; t += 128) {
        int s = t / (NQ * NO), r = t % (NQ * NO);
        xs2[r * GS + s] = x[sb[s] * (NQ * NO) + r];
    }
    __syncthreads();

    if (uni) mlp_body<true >(tid, sj, sb, xs2, zbuf, sVt, lg, out);
    else     mlp_body<false>(tid, sj, sb, xs2, zbuf, sVt, lg, out);
}

// ---------------- launch ----------------
extern "C" void kernel_launch(void* const* d_in, const int* in_sizes, int n_in,
                              void* d_out, int out_size) {
    const float* x   = (const float*)d_in[0];
    const int*   jw  = (const int*)  d_in[1];
    const float* W1  = (const float*)d_in[2];
    const float* W1a = (const float*)d_in[3];
    const float* W2  = (const float*)d_in[4];
    const float* W2a = (const float*)d_in[5];
    const float* V   = (const float*)d_in[6];
    const float* Va  = (const float*)d_in[7];
    float* out = (float*)d_out;

    k_countw <<<PREP_BLOCKS, PREP_THREADS>>>(jw, W1, W1a, W2, W2a, V, Va);
    k_scan   <<<1, 32>>>();
    k_scatter<<<PREP_BLOCKS, PREP_THREADS>>>(jw);
    k_main   <<<NBLOCKS, 128>>>(x, jw, out);
}

// round 15
// speedup vs baseline: 1.7050x; 1.0279x over previous
#include <cuda_runtime.h>

#define NB   16384
#define NJ   12
#define NQ   7
#define NO   5
#define NH1  128
#define NH2  128
#define GS   4
#define NBLOCKS (NB / GS)

#define W1_SZ (NQ * (NO + 1) * NH1)     // 5376
#define W2P_SZ ((NH1 + 1) * NH2)        // 16512 floats
#define W2P_F2 ((NH1 + 1) * 64)         // float2 stride per judge
#define VT_ROW 132                      // [bias, w_1..w_128, 0,0,0]
#define VT_SZ (NQ * NO * VT_ROW)        // 4620
#define ZSTR 36                         // z1 row stride in floats ([k][sp][qpairs])
#define ZBUF_SZ (NH1 * ZSTR)            // 4608 >= 28*VT_ROW (3696)

#define PREP_BLOCKS 64
#define PREP_THREADS 256

// ---------------- device scratch ----------------
__device__ int    g_mode64;
__device__ int    g_count[NJ];          // zero-initialized; re-zeroed by k_scan
__device__ int    g_cursor[NJ];
__device__ int    g_perm[NB];
__device__ float  g_cW1[NJ * W1_SZ];    // [j][q][i=0..5][h]
__device__ float2 g_cW2p[NJ * W2P_F2];  // [j][i=0..128][pair p] = (w[h_lo], w[h_lo+32])
__device__ float  g_cVt[NJ * VT_SZ];    // [j][q][o][i=0..128,pad]

// ---------------- helpers ----------------
__device__ __forceinline__ float sigmoidf(float v) {
    return 1.0f / (1.0f + __expf(-v));
}
__device__ __forceinline__ unsigned long long pk(float a, float b) {
    unsigned long long r;
    asm("mov.b64 %0, {%1, %2};" : "=l"(r) : "f"(a), "f"(b));
    return r;
}
__device__ __forceinline__ void upk(unsigned long long v, float& lo, float& hi) {
    asm("mov.b64 {%0, %1}, %2;" : "=f"(lo), "=f"(hi) : "l"(v));
}
__device__ __forceinline__ void ffma2(unsigned long long& d,
                                      unsigned long long a,
                                      unsigned long long b) {
    asm("fma.rn.f32x2 %0, %1, %2, %0;" : "+l"(d) : "l"(a), "l"(b));
}

// ---------- detect judge-id dtype from the first 512 words ----------
__device__ __forceinline__ int detect_m64(const int* __restrict__ jw, int tid) {
    __shared__ int s_any;
    if (tid == 0) s_any = 0;
    __syncthreads();
    // int64 little-endian ids (0..11): every odd word is 0.
    if (jw[2 * (tid & 255) + 1] != 0) s_any = 1;   // benign race
    __syncthreads();
    return (s_any == 0);
}

// ================= prologue 1: histogram + dtype + weight combine =================
__global__ void __launch_bounds__(PREP_THREADS)
k_countw(const int* __restrict__ jw,
         const float* __restrict__ W1, const float* __restrict__ W1a,
         const float* __restrict__ W2, const float* __restrict__ W2a,
         const float* __restrict__ V,  const float* __restrict__ Va) {
    __shared__ int s_cnt[NJ];
    const int tid = threadIdx.x;
    const int b = blockIdx.x * PREP_THREADS + tid;

    const int m64 = detect_m64(jw, tid);
    if (blockIdx.x == 0 && tid == 0) g_mode64 = m64;

    if (tid < NJ) s_cnt[tid] = 0;
    __syncthreads();
    const int j = m64 ? jw[2 * b] : jw[b];
    atomicAdd(&s_cnt[j], 1);
    __syncthreads();
    if (tid < NJ && s_cnt[tid]) atomicAdd(&g_count[tid], s_cnt[tid]);

    const int n1 = NJ * W1_SZ;
    const int n2 = NJ * W2P_SZ;
    const int n3 = NJ * VT_SZ;
    const int total = n1 + n2 + n3;
    float* w2p = (float*)g_cW2p;
    for (int i = blockIdx.x * PREP_THREADS + tid; i < total;
         i += PREP_BLOCKS * PREP_THREADS) {
        if (i < n1) {
            g_cW1[i] = W1[i % W1_SZ] + W1a[i];
        } else if (i < n1 + n2) {
            int r  = i - n1;                  // [j][i-row][pc], pc in [0,128)
            int jj = r / W2P_SZ;
            int rem = r % W2P_SZ;
            int ii = rem / 128;               // 0 = bias row, 1..128
            int pc = rem % 128;
            int p  = pc >> 1, c = pc & 1;
            int h  = ((p >> 5) << 6) + (p & 31) + (c << 5);  // pair (h_lo, h_lo+32)
            w2p[r] = W2[ii * 128 + h] + W2a[jj * W2P_SZ + ii * 128 + h];
        } else {
            int r = i - n1 - n2;
            int ii = r % VT_ROW;              // 0 = bias, 1..128 = weights
            int rr = r / VT_ROW;              // ((j*NQ+q)*NO+o)
            int o  = rr % NO;
            int qq = (rr / NO) % NQ;
            int jj = rr / (NO * NQ);
            float v = 0.0f;
            if (ii <= NH2)
                v = V[(qq * (NH2 + 1) + ii) * NO + o] +
                    Va[((jj * NQ + qq) * (NH2 + 1) + ii) * NO + o];
            g_cVt[r] = v;
        }
    }
}

// ================= prologue 2: scan + reset =================
__global__ void k_scan() {
    if (threadIdx.x == 0) {
        int acc = 0;
        #pragma unroll
        for (int k = 0; k < NJ; k++) {
            g_cursor[k] = acc;
            acc += g_count[k];
            g_count[k] = 0;
        }
    }
}

// ================= prologue 3: scatter =================
__global__ void __launch_bounds__(PREP_THREADS)
k_scatter(const int* __restrict__ jw) {
    const int tid = threadIdx.x;
    const int b = blockIdx.x * PREP_THREADS + tid;
    const int j = g_mode64 ? jw[2 * b] : jw[b];
    int pos = atomicAdd(&g_cursor[j], 1);
    g_perm[pos] = b;
}

// ================= templated MLP body (UNI = all 4 samples same judge) =================
template <bool UNI>
__device__ __forceinline__ void mlp_body(
    int tid, const int* __restrict__ sj, const int* __restrict__ sb,
    const float* __restrict__ xs2, float* __restrict__ zbuf,
    const float* __restrict__ sVt, float (*__restrict__ lg)[NO],
    float* __restrict__ out) {

    const int j0 = sj[0];
    const float* b1_0 = g_cW1 + j0 * W1_SZ;
    const float* b1_1 = UNI ? b1_0 : g_cW1 + sj[1] * W1_SZ;
    const float* b1_2 = UNI ? b1_0 : g_cW1 + sj[2] * W1_SZ;
    const float* b1_3 = UNI ? b1_0 : g_cW1 + sj[3] * W1_SZ;

    // ---------- layer 1: thread = z1 row k; q processed in PAIRS to cap regs ----------
    // row layout: [sp0: (q0s0,q0s1,q1s0,q1s1)(q2..q3)(q4..q5)(q6s0,q6s1,0,0) | sp1: same s2,s3]
    {
        float* row = zbuf + tid * ZSTR;
        #pragma unroll
        for (int qp = 0; qp < 4; qp++) {
            const int nqp = (qp == 3) ? 1 : 2;     // last pair holds only q6
            float a[GS][2];
            #pragma unroll
            for (int c = 0; c < 2; c++) {
                if (c >= nqp) { a[0][c]=0.f; a[1][c]=0.f; a[2][c]=0.f; a[3][c]=0.f; continue; }
                const int q = 2 * qp + c;
                int off = (q * (NO + 1)) * NH1 + tid;
                a[0][c] = b1_0[off];
                a[1][c] = UNI ? a[0][c] : b1_1[off];
                a[2][c] = UNI ? a[0][c] : b1_2[off];
                a[3][c] = UNI ? a[0][c] : b1_3[off];
                #pragma unroll
                for (int i = 1; i <= NO; i++) {
                    off = (q * (NO + 1) + i) * NH1 + tid;
                    float w0 = b1_0[off];
                    float w1 = UNI ? w0 : b1_1[off];
                    float w2 = UNI ? w0 : b1_2[off];
                    float w3 = UNI ? w0 : b1_3[off];
                    float4 xv = *(const float4*)(xs2 + (q * NO + i - 1) * GS);
                    a[0][c] = fmaf(xv.x, w0, a[0][c]);
                    a[1][c] = fmaf(xv.y, w1, a[1][c]);
                    a[2][c] = fmaf(xv.z, w2, a[2][c]);
                    a[3][c] = fmaf(xv.w, w3, a[3][c]);
                }
            }
            float4 c0, c1;
            if (qp == 3) {
                c0 = make_float4(sigmoidf(a[0][0]), sigmoidf(a[1][0]), 0.f, 0.f);
                c1 = make_float4(sigmoidf(a[2][0]), sigmoidf(a[3][0]), 0.f, 0.f);
            } else {
                c0 = make_float4(sigmoidf(a[0][0]), sigmoidf(a[1][0]),
                                 sigmoidf(a[0][1]), sigmoidf(a[1][1]));
                c1 = make_float4(sigmoidf(a[2][0]), sigmoidf(a[3][0]),
                                 sigmoidf(a[2][1]), sigmoidf(a[3][1]));
            }
            *(float4*)(row + qp * 4)      = c0;    // sp0
            *(float4*)(row + 16 + qp * 4) = c1;    // sp1
        }
    }
    __syncthreads();

    // ---------- layer 2: warp = (sample-pair sp, h-half hw); lane owns (h0, h0+32)
    const int wrp = tid >> 5;
    const int ln  = tid & 31;
    const int sp  = wrp >> 1;                 // 0: samples 0,1  1: samples 2,3
    const int hw  = wrp & 1;                  // h-half
    const int p   = hw * 32 + ln;             // weight-pair index
    const int sA  = 2 * sp, sB = 2 * sp + 1;

    const float2* wpA = g_cW2p + (size_t)(UNI ? j0 : sj[sA]) * W2P_F2 + p;
    const float2* wpB = UNI ? wpA : g_cW2p + (size_t)sj[sB] * W2P_F2 + p;

    unsigned long long acc0[NQ], acc1[NQ];
    {   // bias row i = 0
        float2 wa = wpA[0];
        unsigned long long m0, m1;
        if (UNI) { m0 = pk(wa.x, wa.x); m1 = pk(wa.y, wa.y); }
        else     { float2 wb = wpB[0]; m0 = pk(wa.x, wb.x); m1 = pk(wa.y, wb.y); }
        #pragma unroll
        for (int q = 0; q < NQ; q++) { acc0[q] = m0; acc1[q] = m1; }
    }
    #pragma unroll 4
    for (int i = 1; i <= NH1; i++) {
        float2 wa = wpA[i * 64];
        unsigned long long m0, m1;
        if (UNI) { m0 = pk(wa.x, wa.x); m1 = pk(wa.y, wa.y); }
        else     { float2 wb = wpB[i * 64]; m0 = pk(wa.x, wb.x); m1 = pk(wa.y, wb.y); }
        const float* zb = zbuf + (i - 1) * ZSTR + sp * 16;
        ulonglong2 zA = *(const ulonglong2*)(zb);       // q0, q1 pairs
        ulonglong2 zB = *(const ulonglong2*)(zb + 4);   // q2, q3
        ulonglong2 zC = *(const ulonglong2*)(zb + 8);   // q4, q5
        unsigned long long zD = *(const unsigned long long*)(zb + 12);  // q6
        ffma2(acc0[0], zA.x, m0); ffma2(acc1[0], zA.x, m1);
        ffma2(acc0[1], zA.y, m0); ffma2(acc1[1], zA.y, m1);
        ffma2(acc0[2], zB.x, m0); ffma2(acc1[2], zB.x, m1);
        ffma2(acc0[3], zB.y, m0); ffma2(acc1[3], zB.y, m1);
        ffma2(acc0[4], zC.x, m0); ffma2(acc1[4], zC.x, m1);
        ffma2(acc0[5], zC.y, m0); ffma2(acc1[5], zC.y, m1);
        ffma2(acc0[6], zD,   m0); ffma2(acc1[6], zD,   m1);
    }
    __syncthreads();   // all z1 reads done before z2 overlays zbuf

    {   // sigmoid -> z2 rows
        const int h0 = hw * 64 + ln;
        const int h1 = h0 + 32;
        #pragma unroll
        for (int q = 0; q < NQ; q++) {
            float eA, eB;
            upk(acc0[q], eA, eB);
            zbuf[(sA * NQ + q) * VT_ROW + 1 + h0] = sigmoidf(eA);
            zbuf[(sB * NQ + q) * VT_ROW + 1 + h0] = sigmoidf(eB);
            upk(acc1[q], eA, eB);
            zbuf[(sA * NQ + q) * VT_ROW + 1 + h1] = sigmoidf(eA);
            zbuf[(sB * NQ + q) * VT_ROW + 1 + h1] = sigmoidf(eB);
        }
    }
    if (tid < GS * NQ) {                 // bias + zero pads
        float* row = zbuf + tid * VT_ROW;
        row[0] = 1.0f; row[129] = 0.0f; row[130] = 0.0f; row[131] = 0.0f;
    }
    if (UNI) asm volatile("cp.async.wait_group 0;" ::: "memory");
    __syncthreads();

    // ---------- layer 3: logits (unroll capped to limit live LDS batch) ----------
    for (int t = tid; t < GS * NQ * NO; t += 128) {
        int s = t / (NQ * NO), r = t % (NQ * NO), q = r / NO, o = r % NO;
        const ulonglong2* vz = (const ulonglong2*)(zbuf + (s * NQ + q) * VT_ROW);
        const ulonglong2* vv = UNI
            ? (const ulonglong2*)(sVt + (q * NO + o) * VT_ROW)
            : (const ulonglong2*)(g_cVt + (sj[s] * NQ * NO + q * NO + o) * VT_ROW);
        unsigned long long s0 = 0ULL, s1 = 0ULL;
        #pragma unroll 4
        for (int k = 0; k < VT_ROW / 4; k++) {
            ulonglong2 a = vz[k], bb = vv[k];
            ffma2(s0, a.x, bb.x);
            ffma2(s1, a.y, bb.y);
        }
        float f0, f1, f2, f3;
        upk(s0, f0, f1);
        upk(s1, f2, f3);
        lg[s * NQ + q][o] = (f0 + f1) + (f2 + f3);
    }
    __syncthreads();

    // ---------- softmax + store ----------
    if (tid < GS * NQ) {
        int s = tid / NQ, q = tid % NQ;
        float m = lg[tid][0];
        #pragma unroll
        for (int o = 1; o < NO; o++) m = fmaxf(m, lg[tid][o]);
        float e[NO], sum = 0.f;
        #pragma unroll
        for (int o = 0; o < NO; o++) { e[o] = __expf(lg[tid][o] - m); sum += e[o]; }
        float inv = 1.0f / sum;
        float* op = out + (sb[s] * NQ + q) * NO;
        #pragma unroll
        for (int o = 0; o < NO; o++) op[o] = e[o] * inv;
    }
}

// ================= fused MLP, GS same-judge samples per block =================
__global__ void __launch_bounds__(128, 5)
k_main(const float* __restrict__ x, const int* __restrict__ jw,
       float* __restrict__ out) {
    __shared__ int   sb[GS], sj[GS];
    __shared__ __align__(16) float xs2[NQ * NO * GS];    // [q][o][s0..s3]
    // union: layer1 z1 [k][sp][qpairs] (4608 f)  then  z2 [28][VT_ROW] (3696 f)
    __shared__ __align__(16) float zbuf[ZBUF_SZ];
    __shared__ __align__(16) float sVt[VT_SZ];           // this judge's V^T
    __shared__ float lg[GS * NQ][NO];

    const int tid = threadIdx.x;

    if (tid < GS) {
        int b = g_perm[blockIdx.x * GS + tid];
        sb[tid] = b;
        sj[tid] = g_mode64 ? jw[2 * b] : jw[b];
    }
    __syncthreads();

    const bool uni = (sj[0] == sj[1]) & (sj[1] == sj[2]) & (sj[2] == sj[3]);

    // async prefetch of this judge's V^T (consumed only in layer 3)
    if (uni) {
        unsigned sdst = (unsigned)__cvta_generic_to_shared(sVt);
        unsigned long long gsrc;
        const float* p = g_cVt + sj[0] * VT_SZ;
        asm("cvta.to.global.u64 %0, %1;" : "=l"(gsrc) : "l"(p));
        for (int t = tid; t < VT_SZ / 4; t += 128)
            asm volatile("cp.async.ca.shared.global [%0], [%1], 16;"
                         :: "r"(sdst + t * 16), "l"(gsrc + (unsigned long long)t * 16));
        asm volatile("cp.async.commit_group;");
    }

    // stage x transposed: xs2[(q*5+o)*4 + s]
    for (int t = tid; t < GS * NQ * NO; t += 128) {
        int s = t / (NQ * NO), r = t % (NQ * NO);
        xs2[r * GS + s] = x[sb[s] * (NQ * NO) + r];
    }
    __syncthreads();

    if (uni) mlp_body<true >(tid, sj, sb, xs2, zbuf, sVt, lg, out);
    else     mlp_body<false>(tid, sj, sb, xs2, zbuf, sVt, lg, out);
}

// ---------------- launch ----------------
extern "C" void kernel_launch(void* const* d_in, const int* in_sizes, int n_in,
                              void* d_out, int out_size) {
    const float* x   = (const float*)d_in[0];
    const int*   jw  = (const int*)  d_in[1];
    const float* W1  = (const float*)d_in[2];
    const float* W1a = (const float*)d_in[3];
    const float* W2  = (const float*)d_in[4];
    const float* W2a = (const float*)d_in[5];
    const float* V   = (const float*)d_in[6];
    const float* Va  = (const float*)d_in[7];
    float* out = (float*)d_out;

    k_countw <<<PREP_BLOCKS, PREP_THREADS>>>(jw, W1, W1a, W2, W2a, V, Va);
    k_scan   <<<1, 32>>>();
    k_scatter<<<PREP_BLOCKS, PREP_THREADS>>>(jw);
    k_main   <<<NBLOCKS, 128>>>(x, jw, out);
}